// round 1
// baseline (speedup 1.0000x reference)
#include <cuda_runtime.h>
#include <cstdint>

#define BB 32
#define TT 16
#define HH 32
#define WW 32
#define NN 16384
#define DD 64

// Scratch (no allocations allowed): 2MB keys + per-row select results.
__device__ uint32_t g_keys[BB * NN];
__device__ float    g_rowsum[BB];
__device__ uint32_t g_thr[BB];
__device__ int      g_krem[BB];
__device__ int      g_eqcnt[BB];
__device__ int      g_k[BB];

// ---------------------------------------------------------------------------
// K1: ws = gumbel + marginals, stored as monotonic uint32 keys (desc = larger)
// ---------------------------------------------------------------------------
__global__ void k_ws(const float* __restrict__ u_g, const float* __restrict__ lpt,
                     const float* __restrict__ lph, const float* __restrict__ lpw) {
    int idx = blockIdx.x * blockDim.x + threadIdx.x;
    if (idx < BB) g_rowsum[idx] = 0.f;
    if (idx >= BB * NN) return;
    int b = idx >> 14;
    int n = idx & (NN - 1);
    int t = n >> 10;
    int h = (n >> 5) & 31;
    int w = n & 31;
    float u = u_g[idx];
    float g = -logf(-logf(u));
    // same association as reference: (lpt + lph) + lpw
    float m = (lpt[b * TT + t] + lph[b * HH + h]) + lpw[b * WW + w];
    float ws = g + m;
    uint32_t bits = __float_as_uint(ws);
    uint32_t key = (bits & 0x80000000u) ? ~bits : (bits | 0x80000000u);
    g_keys[idx] = key;
}

// ---------------------------------------------------------------------------
// K2: per-row exact radix select (4 passes x 8 bits). One CTA per row.
// Finds threshold key (= k-th largest), rank-within-equals (krem), eq count.
// ---------------------------------------------------------------------------
__global__ void k_select(const float* __restrict__ u_k) {
    int b = blockIdx.x;
    __shared__ unsigned hist[256];
    __shared__ unsigned suf[256];
    __shared__ uint32_t s_prefix;
    __shared__ int s_krem, s_eqcnt;
    int tid = threadIdx.x;

    // k per row: rates = (u_k + b/31) % 1 ; k = clip(int(N*rates), 1, N-1)
    float r = u_k[0] + (float)b * (1.0f / 31.0f);
    r = r - floorf(r);
    int k = (int)(16384.0f * r);
    k = k < 1 ? 1 : (k > NN - 1 ? NN - 1 : k);

    uint32_t prefix = 0, pmask = 0;
    int krem = k;
    const uint32_t* __restrict__ keys = g_keys + ((size_t)b << 14);

    for (int pass = 0; pass < 4; pass++) {
        int shift = 24 - 8 * pass;
        if (tid < 256) hist[tid] = 0;
        __syncthreads();
        for (int i = tid; i < NN; i += blockDim.x) {
            uint32_t key = keys[i];
            if ((key & pmask) == prefix)
                atomicAdd(&hist[(key >> shift) & 255u], 1u);
        }
        __syncthreads();
        if (tid < 256) suf[tid] = hist[tid];
        __syncthreads();
        // inclusive suffix sums (Hillis-Steele, 8 steps)
        for (int d = 1; d < 256; d <<= 1) {
            unsigned v = 0;
            if (tid < 256) { v = suf[tid]; if (tid + d < 256) v += suf[tid + d]; }
            __syncthreads();
            if (tid < 256) suf[tid] = v;
            __syncthreads();
        }
        if (tid < 256) {
            int above = (int)(suf[tid] - hist[tid]);   // strictly larger keys
            if (above < krem && krem <= (int)suf[tid]) {
                s_prefix = prefix | ((uint32_t)tid << shift);
                s_krem = krem - above;
                if (pass == 3) s_eqcnt = (int)hist[tid];
            }
        }
        __syncthreads();
        prefix = s_prefix;
        krem = s_krem;
        pmask |= (0xFFu << shift);
        __syncthreads();
    }
    if (tid == 0) {
        g_thr[b] = prefix;     // exact value of the k-th largest key
        g_krem[b] = krem;      // how many of the equal-keys (by index) are visible
        g_eqcnt[b] = s_eqcnt;  // how many keys equal the threshold
        g_k[b] = k;
    }
}

// ---------------------------------------------------------------------------
// K3: visibility + masked score row-sums.
// Block = 256 threads = 8 warps; block owns 256 consecutive tokens (same row).
// Phase A: per-lane visibility (coalesced key load + visible store).
// Phase B: warp gathers score rows (256B each) ONLY for masked tokens.
// ---------------------------------------------------------------------------
__global__ void k_mask(const float* __restrict__ score, float* __restrict__ out,
                       int out_size) {
    int base = blockIdx.x * 256;
    int b = base >> 14;
    uint32_t thr = g_thr[b];
    int krem = g_krem[b];
    int eqcnt = g_eqcnt[b];
    int warp = threadIdx.x >> 5, lane = threadIdx.x & 31;
    int tok0 = base + warp * 32;
    int mytok = tok0 + lane;

    uint32_t key = g_keys[mytok];
    bool visible;
    if (key > thr) visible = true;
    else if (key < thr) visible = false;
    else if (eqcnt <= krem) visible = true;  // all ties fit in top-k
    else {
        // rare tie path: stable-sort semantics -> first krem ties by index
        int n = mytok & (NN - 1);
        const uint32_t* __restrict__ row = g_keys + ((size_t)b << 14);
        int cnt = 0;
        for (int i = 0; i < n; i++) cnt += (row[i] == thr);
        visible = cnt < krem;
    }

    if (out_size >= BB * NN) {
        int vis_off = (out_size > BB * NN) ? 1 : 0;  // loss slot first
        out[vis_off + mytok] = visible ? 1.0f : 0.0f;
    }

    unsigned vmask = __ballot_sync(0xffffffffu, visible);
    float wsum = 0.f;
    for (int j = 0; j < 32; j++) {
        if (vmask & (1u << j)) continue;          // visible -> masked out, skip
        const float2* sp = (const float2*)(score + ((size_t)(tok0 + j) << 6));
        float2 v = sp[lane];
        float s = v.x + v.y;
        #pragma unroll
        for (int o = 16; o; o >>= 1) s += __shfl_down_sync(0xffffffffu, s, o);
        if (lane == 0) wsum += s;
    }

    __shared__ float ssum[8];
    if (lane == 0) ssum[warp] = wsum;
    __syncthreads();
    if (threadIdx.x == 0) {
        float tsum = 0.f;
        #pragma unroll
        for (int i = 0; i < 8; i++) tsum += ssum[i];
        atomicAdd(&g_rowsum[b], tsum);
    }
}

// ---------------------------------------------------------------------------
// K4: loss = sum_b rowsum_b * N/(N-k_b) / (B*N*D)
// ---------------------------------------------------------------------------
__global__ void k_final(float* __restrict__ out, int out_size) {
    int b = threadIdx.x;
    float w = g_rowsum[b] * ((float)NN / (float)(NN - g_k[b]));
    #pragma unroll
    for (int o = 16; o; o >>= 1) w += __shfl_down_sync(0xffffffffu, w, o);
    if (threadIdx.x == 0 && out_size != BB * NN) {
        out[0] = w / 33554432.0f;  // B*N*D = 32*16384*64
    }
}

extern "C" void kernel_launch(void* const* d_in, const int* in_sizes, int n_in,
                              void* d_out, int out_size) {
    const float* u_g   = (const float*)d_in[0];
    const float* lpt   = (const float*)d_in[1];
    const float* lph   = (const float*)d_in[2];
    const float* lpw   = (const float*)d_in[3];
    const float* u_k   = (const float*)d_in[4];
    const float* score = (const float*)d_in[5];
    float* out = (float*)d_out;

    k_ws<<<(BB * NN + 255) / 256, 256>>>(u_g, lpt, lph, lpw);
    k_select<<<BB, 1024>>>(u_k);
    k_mask<<<BB * NN / 256, 256>>>(score, out, out_size);
    k_final<<<1, 32>>>(out, out_size);
}

// round 2
// speedup vs baseline: 1.0879x; 1.0879x over previous
#include <cuda_runtime.h>
#include <cstdint>

#define BB 32
#define NN 16384
#define DD 64

// Scratch (no allocations allowed)
__device__ float    g_rowsum[BB];
__device__ int      g_k[BB];
__device__ unsigned g_visbits[BB * (NN / 32)];   // 64KB visibility bitmask
__device__ unsigned g_done;

// ---------------------------------------------------------------------------
// Kernel A: one CTA per row. Computes ws keys (registers + smem shadow),
// exact 4x8-bit radix select from registers, emits visibility bitmask.
// ---------------------------------------------------------------------------
__global__ void __launch_bounds__(1024, 1) k_keys_select(
    const float* __restrict__ u_g, const float* __restrict__ lpt,
    const float* __restrict__ lph, const float* __restrict__ lpw,
    const float* __restrict__ u_k)
{
    extern __shared__ uint32_t skeys[];   // NN words (64KB), for rare tie path
    __shared__ unsigned hist[256];
    __shared__ unsigned suf[256];
    __shared__ uint32_t s_prefix;
    __shared__ int s_krem, s_eqcnt;

    int b = blockIdx.x;
    int tid = threadIdx.x;

    if (tid == 0) {
        g_rowsum[b] = 0.f;
        if (b == 0) g_done = 0u;
    }

    // k per row: rates = (u_k + b/31) % 1 ; k = clip(int(N*rates), 1, N-1)
    float r = u_k[0] + (float)b * (1.0f / 31.0f);
    r = r - floorf(r);
    int k = (int)(16384.0f * r);
    k = k < 1 ? 1 : (k > NN - 1 ? NN - 1 : k);
    if (tid == 0) g_k[b] = k;

    // Element i = s*1024 + tid  =>  t = s, h = tid>>5, w = tid&31
    float lph_v = lph[b * 32 + (tid >> 5)];
    float lpw_v = lpw[b * 32 + (tid & 31)];
    const float* __restrict__ ug = u_g + ((size_t)b << 14);
    const float* __restrict__ lt = lpt + b * 16;

    uint32_t key[16];
    #pragma unroll
    for (int s = 0; s < 16; s++) {
        float u = ug[s * 1024 + tid];
        float g = -logf(-logf(u));
        float m = (lt[s] + lph_v) + lpw_v;     // same association as reference
        float ws = g + m;
        uint32_t bits = __float_as_uint(ws);
        uint32_t kk = (bits & 0x80000000u) ? ~bits : (bits | 0x80000000u);
        key[s] = kk;
        skeys[s * 1024 + tid] = kk;
    }
    __syncthreads();

    // 4-pass radix select on register-resident keys
    uint32_t prefix = 0, pmask = 0;
    int krem = k;
    for (int pass = 0; pass < 4; pass++) {
        int shift = 24 - 8 * pass;
        if (tid < 256) hist[tid] = 0;
        __syncthreads();
        #pragma unroll
        for (int s = 0; s < 16; s++) {
            uint32_t kk = key[s];
            if ((kk & pmask) == prefix)
                atomicAdd(&hist[(kk >> shift) & 255u], 1u);
        }
        __syncthreads();
        if (tid < 256) suf[tid] = hist[tid];
        __syncthreads();
        // inclusive suffix sums (Hillis-Steele)
        for (int d = 1; d < 256; d <<= 1) {
            unsigned v = 0;
            if (tid < 256) { v = suf[tid]; if (tid + d < 256) v += suf[tid + d]; }
            __syncthreads();
            if (tid < 256) suf[tid] = v;
            __syncthreads();
        }
        if (tid < 256) {
            int above = (int)(suf[tid] - hist[tid]);   // strictly larger keys
            if (above < krem && krem <= (int)suf[tid]) {
                s_prefix = prefix | ((uint32_t)tid << shift);
                s_krem = krem - above;
                if (pass == 3) s_eqcnt = (int)hist[tid];
            }
        }
        __syncthreads();
        prefix = s_prefix;
        krem = s_krem;
        pmask |= (0xFFu << shift);
        __syncthreads();
    }

    uint32_t thr = prefix;
    int eqcnt = s_eqcnt;

    // Visibility -> bitmask (one ballot word per 32 consecutive tokens)
    #pragma unroll
    for (int s = 0; s < 16; s++) {
        uint32_t kk = key[s];
        bool vis;
        if (kk > thr) vis = true;
        else if (kk < thr) vis = false;
        else if (eqcnt <= krem) vis = true;          // all ties fit in top-k
        else {
            // rare tie path: stable rank by index among equals (from smem)
            int n = s * 1024 + tid;
            int cnt = 0;
            for (int i = 0; i < n; i++) cnt += (skeys[i] == thr);
            vis = cnt < krem;
        }
        unsigned m = __ballot_sync(0xffffffffu, vis);
        if ((tid & 31) == 0)
            g_visbits[(b << 9) + ((s * 1024 + tid) >> 5)] = m;
    }
}

// ---------------------------------------------------------------------------
// Kernel B: full-chip. Writes visible floats, gathers score rows for masked
// tokens only (256B/row), per-lane accumulation (high MLP), last block
// computes the rate-corrected loss.
// ---------------------------------------------------------------------------
__global__ void __launch_bounds__(256) k_mask_final(
    const float* __restrict__ score, float* __restrict__ out, int out_size)
{
    __shared__ float ssum[8];
    __shared__ bool slast;
    int base = blockIdx.x * 256;
    int b = base >> 14;
    int warp = threadIdx.x >> 5, lane = threadIdx.x & 31;
    int tok0 = base + warp * 32;

    unsigned visword = g_visbits[tok0 >> 5];

    if (out_size >= BB * NN) {
        int off = (out_size > BB * NN) ? 1 : 0;      // loss slot first
        out[off + tok0 + lane] = ((visword >> lane) & 1u) ? 1.0f : 0.0f;
    }

    float acc = 0.f;
    unsigned mw = ~visword;                          // masked tokens
    while (mw) {
        int j = __ffs(mw) - 1;
        mw &= mw - 1u;
        float2 v = ((const float2*)(score + ((size_t)(tok0 + j) << 6)))[lane];
        acc += v.x + v.y;
    }
    #pragma unroll
    for (int o = 16; o; o >>= 1) acc += __shfl_down_sync(0xffffffffu, acc, o);
    if (lane == 0) ssum[warp] = acc;
    __syncthreads();
    if (threadIdx.x == 0) {
        float t = 0.f;
        #pragma unroll
        for (int i = 0; i < 8; i++) t += ssum[i];
        atomicAdd(&g_rowsum[b], t);
        __threadfence();
        unsigned old = atomicAdd(&g_done, 1u);
        slast = (old == gridDim.x - 1);
    }
    __syncthreads();
    if (slast && threadIdx.x < 32) {
        __threadfence();
        float w = g_rowsum[threadIdx.x] *
                  (16384.0f / (float)(NN - g_k[threadIdx.x]));
        #pragma unroll
        for (int o = 16; o; o >>= 1) w += __shfl_down_sync(0xffffffffu, w, o);
        if (threadIdx.x == 0 && out_size != BB * NN)
            out[0] = w / 33554432.0f;                // B*N*D
    }
}

extern "C" void kernel_launch(void* const* d_in, const int* in_sizes, int n_in,
                              void* d_out, int out_size) {
    const float* u_g   = (const float*)d_in[0];
    const float* lpt   = (const float*)d_in[1];
    const float* lph   = (const float*)d_in[2];
    const float* lpw   = (const float*)d_in[3];
    const float* u_k   = (const float*)d_in[4];
    const float* score = (const float*)d_in[5];
    float* out = (float*)d_out;

    cudaFuncSetAttribute(k_keys_select,
                         cudaFuncAttributeMaxDynamicSharedMemorySize, 65536);

    k_keys_select<<<BB, 1024, 65536>>>(u_g, lpt, lph, lpw, u_k);
    k_mask_final<<<BB * NN / 256, 256>>>(score, out, out_size);
}

// round 3
// speedup vs baseline: 1.5785x; 1.4510x over previous
#include <cuda_runtime.h>
#include <cstdint>

#define BB 32
#define NN 16384
#define DD 64

// Scratch (no allocations allowed)
__device__ float    g_rowsum[BB];
__device__ int      g_k[BB];
__device__ unsigned g_visbits[BB * (NN / 32)];   // 64KB visibility bitmask
__device__ unsigned g_done;

// ---------------------------------------------------------------------------
// Kernel A: one CTA per row. Computes ws keys (registers + smem shadow),
// exact 4x8-bit radix select from registers, emits visibility bitmask.
// ---------------------------------------------------------------------------
__global__ void __launch_bounds__(1024, 1) k_keys_select(
    const float* __restrict__ u_g, const float* __restrict__ lpt,
    const float* __restrict__ lph, const float* __restrict__ lpw,
    const float* __restrict__ u_k)
{
    extern __shared__ uint32_t skeys[];   // NN words (64KB), for rare tie path
    __shared__ unsigned hist[256];
    __shared__ unsigned suf[256];
    __shared__ uint32_t s_prefix;
    __shared__ int s_krem, s_eqcnt;

    int b = blockIdx.x;
    int tid = threadIdx.x;

    if (tid == 0) {
        g_rowsum[b] = 0.f;
        if (b == 0) g_done = 0u;
    }

    // k per row: rates = (u_k + b/31) % 1 ; k = clip(int(N*rates), 1, N-1)
    float r = u_k[0] + (float)b * (1.0f / 31.0f);
    r = r - floorf(r);
    int k = (int)(16384.0f * r);
    k = k < 1 ? 1 : (k > NN - 1 ? NN - 1 : k);
    if (tid == 0) g_k[b] = k;

    // Element i = s*1024 + tid  =>  t = s, h = tid>>5, w = tid&31
    float lph_v = lph[b * 32 + (tid >> 5)];
    float lpw_v = lpw[b * 32 + (tid & 31)];
    const float* __restrict__ ug = u_g + ((size_t)b << 14);
    const float* __restrict__ lt = lpt + b * 16;

    uint32_t key[16];
    #pragma unroll
    for (int s = 0; s < 16; s++) {
        float u = ug[s * 1024 + tid];
        float g = -logf(-logf(u));
        float m = (lt[s] + lph_v) + lpw_v;     // same association as reference
        float ws = g + m;
        uint32_t bits = __float_as_uint(ws);
        uint32_t kk = (bits & 0x80000000u) ? ~bits : (bits | 0x80000000u);
        key[s] = kk;
        skeys[s * 1024 + tid] = kk;
    }
    __syncthreads();

    // 4-pass radix select on register-resident keys
    uint32_t prefix = 0, pmask = 0;
    int krem = k;
    for (int pass = 0; pass < 4; pass++) {
        int shift = 24 - 8 * pass;
        if (tid < 256) hist[tid] = 0;
        __syncthreads();
        #pragma unroll
        for (int s = 0; s < 16; s++) {
            uint32_t kk = key[s];
            if ((kk & pmask) == prefix)
                atomicAdd(&hist[(kk >> shift) & 255u], 1u);
        }
        __syncthreads();
        if (tid < 256) suf[tid] = hist[tid];
        __syncthreads();
        // inclusive suffix sums (Hillis-Steele)
        for (int d = 1; d < 256; d <<= 1) {
            unsigned v = 0;
            if (tid < 256) { v = suf[tid]; if (tid + d < 256) v += suf[tid + d]; }
            __syncthreads();
            if (tid < 256) suf[tid] = v;
            __syncthreads();
        }
        if (tid < 256) {
            int above = (int)(suf[tid] - hist[tid]);   // strictly larger keys
            if (above < krem && krem <= (int)suf[tid]) {
                s_prefix = prefix | ((uint32_t)tid << shift);
                s_krem = krem - above;
                if (pass == 3) s_eqcnt = (int)hist[tid];
            }
        }
        __syncthreads();
        prefix = s_prefix;
        krem = s_krem;
        pmask |= (0xFFu << shift);
        __syncthreads();
    }

    uint32_t thr = prefix;
    int eqcnt = s_eqcnt;

    // Visibility -> bitmask (one ballot word per 32 consecutive tokens)
    #pragma unroll
    for (int s = 0; s < 16; s++) {
        uint32_t kk = key[s];
        bool vis;
        if (kk > thr) vis = true;
        else if (kk < thr) vis = false;
        else if (eqcnt <= krem) vis = true;          // all ties fit in top-k
        else {
            // rare tie path: stable rank by index among equals (from smem)
            int n = s * 1024 + tid;
            int cnt = 0;
            for (int i = 0; i < n; i++) cnt += (skeys[i] == thr);
            vis = cnt < krem;
        }
        unsigned m = __ballot_sync(0xffffffffu, vis);
        if ((tid & 31) == 0)
            g_visbits[(b << 9) + ((s * 1024 + tid) >> 5)] = m;
    }
}

// ---------------------------------------------------------------------------
// Kernel B: full-chip. Writes visible floats; gathers score rows for masked
// tokens via a FULLY UNROLLED predicated loop (32 independent LDG.64 ->
// high MLP), 4 rotating accumulators; last block computes the loss.
// ---------------------------------------------------------------------------
__global__ void __launch_bounds__(256) k_mask_final(
    const float* __restrict__ score, float* __restrict__ out, int out_size)
{
    __shared__ float ssum[8];
    __shared__ bool slast;
    int base = blockIdx.x * 256;
    int b = base >> 14;
    int warp = threadIdx.x >> 5, lane = threadIdx.x & 31;
    int tok0 = base + warp * 32;

    unsigned visword = g_visbits[tok0 >> 5];

    if (out_size >= BB * NN) {
        int off = (out_size > BB * NN) ? 1 : 0;      // loss slot first
        out[off + tok0 + lane] = ((visword >> lane) & 1u) ? 1.0f : 0.0f;
    }

    // Warp's 32 token rows start here; each row = 32 float2 (256B), lane-th pair.
    const float2* __restrict__ rows =
        (const float2*)score + (((size_t)tok0) << 5) + lane;

    float a0 = 0.f, a1 = 0.f, a2 = 0.f, a3 = 0.f;
    #pragma unroll
    for (int j = 0; j < 32; j += 4) {
        float2 v0 = make_float2(0.f, 0.f), v1 = v0, v2 = v0, v3 = v0;
        if (!((visword >> (j + 0)) & 1u)) v0 = rows[(size_t)(j + 0) << 5];
        if (!((visword >> (j + 1)) & 1u)) v1 = rows[(size_t)(j + 1) << 5];
        if (!((visword >> (j + 2)) & 1u)) v2 = rows[(size_t)(j + 2) << 5];
        if (!((visword >> (j + 3)) & 1u)) v3 = rows[(size_t)(j + 3) << 5];
        a0 += v0.x + v0.y;
        a1 += v1.x + v1.y;
        a2 += v2.x + v2.y;
        a3 += v3.x + v3.y;
    }
    float acc = (a0 + a1) + (a2 + a3);
    #pragma unroll
    for (int o = 16; o; o >>= 1) acc += __shfl_down_sync(0xffffffffu, acc, o);
    if (lane == 0) ssum[warp] = acc;
    __syncthreads();
    if (threadIdx.x == 0) {
        float t = 0.f;
        #pragma unroll
        for (int i = 0; i < 8; i++) t += ssum[i];
        atomicAdd(&g_rowsum[b], t);
        __threadfence();
        unsigned old = atomicAdd(&g_done, 1u);
        slast = (old == gridDim.x - 1);
    }
    __syncthreads();
    if (slast && threadIdx.x < 32) {
        __threadfence();
        float w = g_rowsum[threadIdx.x] *
                  (16384.0f / (float)(NN - g_k[threadIdx.x]));
        #pragma unroll
        for (int o = 16; o; o >>= 1) w += __shfl_down_sync(0xffffffffu, w, o);
        if (threadIdx.x == 0 && out_size != BB * NN)
            out[0] = w / 33554432.0f;                // B*N*D
    }
}

extern "C" void kernel_launch(void* const* d_in, const int* in_sizes, int n_in,
                              void* d_out, int out_size) {
    const float* u_g   = (const float*)d_in[0];
    const float* lpt   = (const float*)d_in[1];
    const float* lph   = (const float*)d_in[2];
    const float* lpw   = (const float*)d_in[3];
    const float* u_k   = (const float*)d_in[4];
    const float* score = (const float*)d_in[5];
    float* out = (float*)d_out;

    cudaFuncSetAttribute(k_keys_select,
                         cudaFuncAttributeMaxDynamicSharedMemorySize, 65536);

    k_keys_select<<<BB, 1024, 65536>>>(u_g, lpt, lph, lpw, u_k);
    k_mask_final<<<BB * NN / 256, 256>>>(score, out, out_size);
}